// round 7
// baseline (speedup 1.0000x reference)
#include <cuda_runtime.h>
#include <cuda_bf16.h>
#include <cstdint>
#include <math.h>

// Problem constants
#define BBX 4
#define LLX 4096
#define CCX 512
#define HHX 16
#define HDX 32
#define KWX 13
#define KHX 6
#define NRPBX 25
#define MLX (BBX*LLX)          // 16384
#define KK  512

// ---------------------------------------------------------------------------
// Global scratch
// ---------------------------------------------------------------------------
__device__ float g_qkv[(size_t)MLX * (3 * CCX)];
__device__ __nv_bfloat16 g_xa_hi[(size_t)MLX * CCX];
__device__ __nv_bfloat16 g_xa_lo[(size_t)MLX * CCX];
__device__ __nv_bfloat16 g_at_hi[(size_t)MLX * CCX];
__device__ __nv_bfloat16 g_at_lo[(size_t)MLX * CCX];
__device__ __nv_bfloat16 g_w1_hi[(size_t)(3*CCX) * CCX];
__device__ __nv_bfloat16 g_w1_lo[(size_t)(3*CCX) * CCX];
__device__ __nv_bfloat16 g_w2_hi[(size_t)CCX * CCX];
__device__ __nv_bfloat16 g_w2_lo[(size_t)CCX * CCX];

// ---------------------------------------------------------------------------
// Helpers
// ---------------------------------------------------------------------------
__device__ __forceinline__ uint32_t sptr(const void* p) {
    return (uint32_t)__cvta_generic_to_shared(p);
}
__device__ __forceinline__ void cp16(uint32_t s, const void* g) {
    asm volatile("cp.async.cg.shared.global [%0], [%1], 16;\n" :: "r"(s), "l"(g));
}
__device__ __forceinline__ void cp_commit() {
    asm volatile("cp.async.commit_group;\n" ::: "memory");
}
__device__ __forceinline__ void cp_wait0() {
    asm volatile("cp.async.wait_group 0;\n" ::: "memory");
}
__device__ __forceinline__ void mma_bf16(float* c, const uint32_t* a, const uint32_t* b) {
    asm volatile(
        "mma.sync.aligned.m16n8k16.row.col.f32.bf16.bf16.f32 "
        "{%0,%1,%2,%3}, {%4,%5,%6,%7}, {%8,%9}, {%0,%1,%2,%3};\n"
        : "+f"(c[0]), "+f"(c[1]), "+f"(c[2]), "+f"(c[3])
        : "r"(a[0]), "r"(a[1]), "r"(a[2]), "r"(a[3]), "r"(b[0]), "r"(b[1]));
}
__device__ __forceinline__ void bf16split(float x, __nv_bfloat16& h, __nv_bfloat16& l) {
    h = __float2bfloat16(x);
    l = __float2bfloat16(x - __bfloat162float(h));
}

// ---------------------------------------------------------------------------
// bf16x3 GEMM, warp tile 64x64, 3-pass MMA ordering (no RAW chains).
// 128x128 CTA tile, 128 threads (4 warps, 2x2), BK=32 bf16, 2-stage cp.async.
// ---------------------------------------------------------------------------
#define RSTR 40                      // bf16 row stride (80 B, conflict-free)
#define TILE_B (128u * RSTR * 2u)    // 10240 B
#define STAGE_B (4u * TILE_B)        // 40960 B
#define GEMM_SMEM (2u * STAGE_B)     // 81920 B

__global__ __launch_bounds__(128, 2)
void bf16x3_gemm(const __nv_bfloat16* __restrict__ Ahi, const __nv_bfloat16* __restrict__ Alo,
                 const __nv_bfloat16* __restrict__ Bhi, const __nv_bfloat16* __restrict__ Blo,
                 const float* __restrict__ bias, float* __restrict__ C, int N)
{
    extern __shared__ char smem[];

    const int tid  = threadIdx.x;
    const int warp = tid >> 5;     // 0..3
    const int lane = tid & 31;
    const int wm   = warp & 1;     // 64-row slab
    const int wn   = warp >> 1;    // 64-col slab
    const int gid  = lane >> 2;    // 0..7
    const int tg   = lane & 3;     // 0..3

    const int bm0 = blockIdx.y * 128;
    const int bn0 = blockIdx.x * 128;

    // loader: warp w loads operand w (0=Ah 1=Al 2=Bh 3=Bl), 128 rows x 64 B
    const __nv_bfloat16* lsrc = (warp == 0) ? Ahi : (warp == 1) ? Alo
                              : (warp == 2) ? Bhi : Blo;
    const int lrow0 = (warp < 2) ? bm0 : bn0;
    const __nv_bfloat16* gsrc = lsrc + (size_t)lrow0 * KK;
    const uint32_t tbase = sptr(smem) + (uint32_t)warp * TILE_B;

    #define LOADCHUNK(c, bufb) do { \
        const __nv_bfloat16* gp0 = gsrc + (c) * 32; \
        const uint32_t sm0 = tbase + (bufb) * STAGE_B; \
        _Pragma("unroll") \
        for (int i_ = 0; i_ < 16; i_++) { \
            int u_ = i_ * 32 + lane; \
            int row_ = u_ >> 2; \
            int c16_ = u_ & 3; \
            cp16(sm0 + (uint32_t)(row_ * (RSTR * 2) + c16_ * 16), \
                 gp0 + (size_t)row_ * KK + c16_ * 8); \
        } \
        cp_commit(); \
    } while (0)

    float acc[4][8][4];
    #pragma unroll
    for (int mt = 0; mt < 4; mt++)
        #pragma unroll
        for (int nt = 0; nt < 8; nt++)
            #pragma unroll
            for (int c = 0; c < 4; c++) acc[mt][nt][c] = 0.f;

    const int nT = KK / 32;          // 16

    LOADCHUNK(0, 0);

    for (int t = 0; t < nT; t++) {
        cp_wait0();
        __syncthreads();
        const int cur = t & 1;

        if (t + 1 < nT) LOADCHUNK(t + 1, cur ^ 1);

        const char* stage = smem + cur * STAGE_B;
        const char* pAh = stage;
        const char* pAl = stage + TILE_B;
        const char* pBh = stage + 2 * TILE_B;
        const char* pBl = stage + 3 * TILE_B;

        #pragma unroll
        for (int ks = 0; ks < 2; ks++) {
            const int kb = ks * 32 + tg * 4;

            // ---- load ALL fragments for this k16 step (independent LDS burst)
            uint32_t bh[8][2], bl[8][2];
            #pragma unroll
            for (int nt = 0; nt < 8; nt++) {
                const int col = wn * 64 + nt * 8 + gid;
                const int o = col * (RSTR * 2) + kb;
                bh[nt][0] = *(const uint32_t*)(pBh + o);
                bh[nt][1] = *(const uint32_t*)(pBh + o + 16);
                bl[nt][0] = *(const uint32_t*)(pBl + o);
                bl[nt][1] = *(const uint32_t*)(pBl + o + 16);
            }
            uint32_t ah[4][4], al[4][4];
            #pragma unroll
            for (int mt = 0; mt < 4; mt++) {
                const int r0 = (wm * 64 + mt * 16 + gid) * (RSTR * 2) + kb;
                const int r1 = r0 + 8 * (RSTR * 2);
                ah[mt][0] = *(const uint32_t*)(pAh + r0);
                ah[mt][1] = *(const uint32_t*)(pAh + r1);
                ah[mt][2] = *(const uint32_t*)(pAh + r0 + 16);
                ah[mt][3] = *(const uint32_t*)(pAh + r1 + 16);
                al[mt][0] = *(const uint32_t*)(pAl + r0);
                al[mt][1] = *(const uint32_t*)(pAl + r1);
                al[mt][2] = *(const uint32_t*)(pAl + r0 + 16);
                al[mt][3] = *(const uint32_t*)(pAl + r1 + 16);
            }

            // ---- pass 1: hi*hi (32 independent MMAs)
            #pragma unroll
            for (int mt = 0; mt < 4; mt++)
                #pragma unroll
                for (int nt = 0; nt < 8; nt++)
                    mma_bf16(acc[mt][nt], ah[mt], bh[nt]);
            // ---- pass 2: hi*lo
            #pragma unroll
            for (int mt = 0; mt < 4; mt++)
                #pragma unroll
                for (int nt = 0; nt < 8; nt++)
                    mma_bf16(acc[mt][nt], ah[mt], bl[nt]);
            // ---- pass 3: lo*hi
            #pragma unroll
            for (int mt = 0; mt < 4; mt++)
                #pragma unroll
                for (int nt = 0; nt < 8; nt++)
                    mma_bf16(acc[mt][nt], al[mt], bh[nt]);
        }
        __syncthreads();
    }
    #undef LOADCHUNK

    // epilogue
    #pragma unroll
    for (int nt = 0; nt < 8; nt++) {
        const int col = bn0 + wn * 64 + nt * 8 + tg * 2;
        const float2 bv = *(const float2*)(bias + col);
        #pragma unroll
        for (int mt = 0; mt < 4; mt++) {
            const int r0 = bm0 + wm * 64 + mt * 16 + gid;
            float2 o0 = make_float2(acc[mt][nt][0] + bv.x, acc[mt][nt][1] + bv.y);
            float2 o1 = make_float2(acc[mt][nt][2] + bv.x, acc[mt][nt][3] + bv.y);
            *(float2*)(C + (size_t)r0 * N + col)       = o0;
            *(float2*)(C + (size_t)(r0 + 8) * N + col) = o1;
        }
    }
}

// ---------------------------------------------------------------------------
// Elementwise split to bf16 hi/lo
// ---------------------------------------------------------------------------
__global__ __launch_bounds__(256)
void split_kernel(const float* __restrict__ in, __nv_bfloat16* __restrict__ hi,
                  __nv_bfloat16* __restrict__ lo, int n4)
{
    int i = blockIdx.x * 256 + threadIdx.x;
    if (i >= n4) return;
    float4 v = ((const float4*)in)[i];
    __nv_bfloat16 h0, h1, h2, h3, l0, l1, l2, l3;
    bf16split(v.x, h0, l0); bf16split(v.y, h1, l1);
    bf16split(v.z, h2, l2); bf16split(v.w, h3, l3);
    __nv_bfloat162 hp0 = __nv_bfloat162(h0, h1), hp1 = __nv_bfloat162(h2, h3);
    __nv_bfloat162 lp0 = __nv_bfloat162(l0, l1), lp1 = __nv_bfloat162(l2, l3);
    ((uint2*)hi)[i] = make_uint2(*(uint32_t*)&hp0, *(uint32_t*)&hp1);
    ((uint2*)lo)[i] = make_uint2(*(uint32_t*)&lp0, *(uint32_t*)&lp1);
}

// ---------------------------------------------------------------------------
// Transpose + split: w[512, Ndim] -> hi/lo [Ndim, 512] bf16
// ---------------------------------------------------------------------------
__global__ __launch_bounds__(256)
void splitT_kernel(const float* __restrict__ w, __nv_bfloat16* __restrict__ hi,
                   __nv_bfloat16* __restrict__ lo, int Ndim)
{
    __shared__ float t[32][33];
    const int k0 = blockIdx.x * 32;
    const int n0 = blockIdx.y * 32;
    const int tx = threadIdx.x, ty = threadIdx.y;
    #pragma unroll
    for (int r = 0; r < 32; r += 8)
        t[ty + r][tx] = w[(size_t)(k0 + ty + r) * Ndim + n0 + tx];
    __syncthreads();
    #pragma unroll
    for (int r = 0; r < 32; r += 8) {
        float v = t[tx][ty + r];
        __nv_bfloat16 h, l;
        bf16split(v, h, l);
        const size_t idx = (size_t)(n0 + ty + r) * KK + k0 + tx;
        hi[idx] = h;
        lo[idx] = l;
    }
}

// ---------------------------------------------------------------------------
// Neighborhood attention: thread-per-l, stride-33 smem, writes bf16 split out
// ---------------------------------------------------------------------------
#define LT 128
#define WR (LT + KWX - 1)       // 140
#define SSTR 33

__global__ __launch_bounds__(128)
void natten1d_kernel(const float* __restrict__ rpb)
{
    __shared__ float sk[WR * SSTR];
    __shared__ float sv[WR * SSTR];
    __shared__ float srpb[NRPBX];

    const int tid  = threadIdx.x;
    const int warp = tid >> 5;
    const int lane = tid & 31;
    const int l0 = blockIdx.x * LT;
    const int h  = blockIdx.y;
    const int b  = blockIdx.z;
    const int base = l0 - KHX;

    const float* qb = g_qkv + (size_t)b * LLX * (3 * CCX) + h * HDX;
    const float* kb = qb + CCX;
    const float* vb = qb + 2 * CCX;

    if (tid < NRPBX) srpb[tid] = rpb[h * NRPBX + tid];

    for (int r = warp; r < WR; r += 4) {
        const int gr = base + r;
        if (gr >= 0 && gr < LLX) {
            sk[r * SSTR + lane] = kb[(size_t)gr * (3 * CCX) + lane];
            sv[r * SSTR + lane] = vb[(size_t)gr * (3 * CCX) + lane];
        }
    }
    __syncthreads();

    const int l = l0 + tid;
    int ni = l - KHX;
    if (ni < 0) ni = 0;
    if (ni > LLX - KWX) ni = LLX - KWX;
    const int roff = ni - l + (KWX - 1);
    const int s0 = ni - base;

    const float scale = 0.17677669529663687f;
    float q[HDX];
    {
        const float* qp = qb + (size_t)l * (3 * CCX);
        #pragma unroll
        for (int d4 = 0; d4 < HDX; d4 += 4) {
            float4 v = *(const float4*)(qp + d4);
            q[d4 + 0] = v.x * scale; q[d4 + 1] = v.y * scale;
            q[d4 + 2] = v.z * scale; q[d4 + 3] = v.w * scale;
        }
    }

    float sc[KWX];
    float smax = -1e30f;
    #pragma unroll
    for (int j = 0; j < KWX; j++) {
        const float* kr = &sk[(s0 + j) * SSTR];
        float s = 0.f;
        #pragma unroll
        for (int d = 0; d < HDX; d++) s = fmaf(q[d], kr[d], s);
        s += srpb[roff + j];
        sc[j] = s;
        smax = fmaxf(smax, s);
    }
    float ssum = 0.f;
    #pragma unroll
    for (int j = 0; j < KWX; j++) {
        sc[j] = __expf(sc[j] - smax);
        ssum += sc[j];
    }
    const float inv = 1.f / ssum;

    float acc[HDX];
    #pragma unroll
    for (int d = 0; d < HDX; d++) acc[d] = 0.f;
    #pragma unroll
    for (int j = 0; j < KWX; j++) {
        const float* vr = &sv[(s0 + j) * SSTR];
        const float p = sc[j];
        #pragma unroll
        for (int d = 0; d < HDX; d++) acc[d] = fmaf(p, vr[d], acc[d]);
    }

    __nv_bfloat16* oh = g_at_hi + (size_t)(b * LLX + l) * CCX + h * HDX;
    __nv_bfloat16* ol = g_at_lo + (size_t)(b * LLX + l) * CCX + h * HDX;
    #pragma unroll
    for (int d2 = 0; d2 < HDX; d2 += 2) {
        __nv_bfloat16 h0, h1, l0b, l1b;
        bf16split(acc[d2 + 0] * inv, h0, l0b);
        bf16split(acc[d2 + 1] * inv, h1, l1b);
        __nv_bfloat162 hp = __nv_bfloat162(h0, h1);
        __nv_bfloat162 lp = __nv_bfloat162(l0b, l1b);
        *(uint32_t*)(oh + d2) = *(uint32_t*)&hp;
        *(uint32_t*)(ol + d2) = *(uint32_t*)&lp;
    }
}

// ---------------------------------------------------------------------------
extern "C" void kernel_launch(void* const* d_in, const int* in_sizes, int n_in,
                              void* d_out, int out_size)
{
    const float* x      = (const float*)d_in[0];
    const float* qkv_w  = (const float*)d_in[1];
    const float* qkv_b  = (const float*)d_in[2];
    const float* rpb    = (const float*)d_in[3];
    const float* proj_w = (const float*)d_in[4];
    const float* proj_b = (const float*)d_in[5];
    float* out = (float*)d_out;

    float* qkv;
    __nv_bfloat16 *xh, *xl, *ah, *al, *w1h, *w1l, *w2h, *w2l;
    cudaGetSymbolAddress((void**)&qkv, g_qkv);
    cudaGetSymbolAddress((void**)&xh,  g_xa_hi);
    cudaGetSymbolAddress((void**)&xl,  g_xa_lo);
    cudaGetSymbolAddress((void**)&ah,  g_at_hi);
    cudaGetSymbolAddress((void**)&al,  g_at_lo);
    cudaGetSymbolAddress((void**)&w1h, g_w1_hi);
    cudaGetSymbolAddress((void**)&w1l, g_w1_lo);
    cudaGetSymbolAddress((void**)&w2h, g_w2_hi);
    cudaGetSymbolAddress((void**)&w2l, g_w2_lo);

    cudaFuncSetAttribute(bf16x3_gemm,
                         cudaFuncAttributeMaxDynamicSharedMemorySize, GEMM_SMEM);

    // 1) splits
    {
        int n4 = MLX * CCX / 4;
        split_kernel<<<(n4 + 255) / 256, 256>>>(x, xh, xl, n4);
    }
    {
        dim3 grid(KK / 32, (3 * CCX) / 32);
        splitT_kernel<<<grid, dim3(32, 8)>>>(qkv_w, w1h, w1l, 3 * CCX);
    }
    {
        dim3 grid(KK / 32, CCX / 32);
        splitT_kernel<<<grid, dim3(32, 8)>>>(proj_w, w2h, w2l, CCX);
    }

    // 2) QKV GEMM
    {
        dim3 grid((3 * CCX) / 128, MLX / 128);
        bf16x3_gemm<<<grid, 128, GEMM_SMEM>>>(xh, xl, w1h, w1l, qkv_b, qkv, 3 * CCX);
    }

    // 3) attention
    {
        dim3 grid(LLX / LT, HHX, BBX);
        natten1d_kernel<<<grid, 128>>>(rpb);
    }

    // 4) proj GEMM
    {
        dim3 grid(CCX / 128, MLX / 128);
        bf16x3_gemm<<<grid, 128, GEMM_SMEM>>>(ah, al, w2h, w2l, proj_b, out, CCX);
    }
}

// round 8
// speedup vs baseline: 1.3697x; 1.3697x over previous
#include <cuda_runtime.h>
#include <cuda_fp16.h>
#include <cstdint>
#include <math.h>

// Problem constants
#define BBX 4
#define LLX 4096
#define CCX 512
#define HHX 16
#define HDX 32
#define KWX 13
#define KHX 6
#define NRPBX 25
#define MLX (BBX*LLX)          // 16384
#define KK  512

// ---------------------------------------------------------------------------
// Global scratch
// ---------------------------------------------------------------------------
__device__ float g_qkv[(size_t)MLX * (3 * CCX)];
__device__ __half g_xa[(size_t)MLX * CCX];             // x as fp16 (A of GEMM1)
__device__ __half g_at[(size_t)MLX * CCX];             // attn out fp16 (A of GEMM2)
__device__ __half g_w1_hi[(size_t)(3*CCX) * CCX];      // qkv_w^T [1536,512]
__device__ __half g_w1_lo[(size_t)(3*CCX) * CCX];
__device__ __half g_w2_hi[(size_t)CCX * CCX];          // proj_w^T [512,512]
__device__ __half g_w2_lo[(size_t)CCX * CCX];

// ---------------------------------------------------------------------------
// Helpers
// ---------------------------------------------------------------------------
__device__ __forceinline__ uint32_t sptr(const void* p) {
    return (uint32_t)__cvta_generic_to_shared(p);
}
__device__ __forceinline__ void cp16(uint32_t s, const void* g) {
    asm volatile("cp.async.cg.shared.global [%0], [%1], 16;\n" :: "r"(s), "l"(g));
}
__device__ __forceinline__ void cp_commit() {
    asm volatile("cp.async.commit_group;\n" ::: "memory");
}
__device__ __forceinline__ void cp_wait0() {
    asm volatile("cp.async.wait_group 0;\n" ::: "memory");
}
__device__ __forceinline__ void cp_wait1() {
    asm volatile("cp.async.wait_group 1;\n" ::: "memory");
}
__device__ __forceinline__ void mma_f16(float* c, const uint32_t* a, const uint32_t* b) {
    asm volatile(
        "mma.sync.aligned.m16n8k16.row.col.f32.f16.f16.f32 "
        "{%0,%1,%2,%3}, {%4,%5,%6,%7}, {%8,%9}, {%0,%1,%2,%3};\n"
        : "+f"(c[0]), "+f"(c[1]), "+f"(c[2]), "+f"(c[3])
        : "r"(a[0]), "r"(a[1]), "r"(a[2]), "r"(a[3]), "r"(b[0]), "r"(b[1]));
}
__device__ __forceinline__ void fp16split(float x, __half& h, __half& l) {
    h = __float2half_rn(x);
    l = __float2half_rn(x - __half2float(h));
}

// ---------------------------------------------------------------------------
// fp16x2 GEMM (asymmetric split): C[M,N] = A[M,512] x ((Bhi+Blo)[N,512])^T + bias
// A plain fp16; B = hi + lo fp16. Per k16 step: 2 MMAs (a*bh, a*bl).
// 128x128 CTA tile, 128 threads (4 warps, 2x2, warp tile 64x64),
// BK=32, 3-stage cp.async ring.
// ---------------------------------------------------------------------------
#define RSTR 40                      // fp16 row stride (80 B, conflict-free)
#define TILE_B (128u * RSTR * 2u)    // 10240 B
#define STAGE_B (3u * TILE_B)        // 30720 B  (A, Bhi, Blo)
#define GEMM_SMEM (3u * STAGE_B)     // 92160 B  (3 stages)

__global__ __launch_bounds__(128, 2)
void fp16x2_gemm(const __half* __restrict__ A,
                 const __half* __restrict__ Bhi, const __half* __restrict__ Blo,
                 const float* __restrict__ bias, float* __restrict__ C, int N)
{
    extern __shared__ char smem[];

    const int tid  = threadIdx.x;
    const int warp = tid >> 5;     // 0..3
    const int lane = tid & 31;
    const int wm   = warp & 1;     // 64-row slab
    const int wn   = warp >> 1;    // 64-col slab
    const int gid  = lane >> 2;    // 0..7
    const int tg   = lane & 3;     // 0..3

    const int bm0 = blockIdx.y * 128;
    const int bn0 = blockIdx.x * 128;

    const __half* t0 = A   + (size_t)bm0 * KK;   // A tile rows
    const __half* t1 = Bhi + (size_t)bn0 * KK;   // B hi rows
    const __half* t2 = Blo + (size_t)bn0 * KK;   // B lo rows
    const uint32_t sbase = sptr(smem);

    // 3 tiles x 512 cp16-units; 128 threads -> 4 units per thread per tile
    #define LOADCHUNK(c, bufb) do { \
        const uint32_t sm0 = sbase + (bufb) * STAGE_B; \
        const __half* gp0 = t0 + (c) * 32; \
        const __half* gp1 = t1 + (c) * 32; \
        const __half* gp2 = t2 + (c) * 32; \
        _Pragma("unroll") \
        for (int i_ = 0; i_ < 4; i_++) { \
            int u_ = i_ * 128 + tid; \
            int row_ = u_ >> 2; \
            int c16_ = u_ & 3; \
            uint32_t so_ = (uint32_t)(row_ * (RSTR * 2) + c16_ * 16); \
            size_t go_ = (size_t)row_ * KK + c16_ * 8; \
            cp16(sm0 + so_,                gp0 + go_); \
            cp16(sm0 + TILE_B + so_,       gp1 + go_); \
            cp16(sm0 + 2 * TILE_B + so_,   gp2 + go_); \
        } \
        cp_commit(); \
    } while (0)

    float acc[4][8][4];
    #pragma unroll
    for (int mt = 0; mt < 4; mt++)
        #pragma unroll
        for (int nt = 0; nt < 8; nt++)
            #pragma unroll
            for (int c = 0; c < 4; c++) acc[mt][nt][c] = 0.f;

    const int nT = KK / 32;          // 16

    LOADCHUNK(0, 0);
    LOADCHUNK(1, 1);

    int cb = 0, pb = 2;
    for (int t = 0; t < nT; t++) {
        if (t == nT - 1) cp_wait0(); else cp_wait1();
        __syncthreads();

        if (t + 2 < nT) LOADCHUNK(t + 2, pb);

        const char* stage = smem + (uint32_t)cb * STAGE_B;
        const char* pA  = stage;
        const char* pBh = stage + TILE_B;
        const char* pBl = stage + 2 * TILE_B;

        #pragma unroll
        for (int ks = 0; ks < 2; ks++) {
            const int kb = ks * 32 + tg * 4;

            uint32_t bh[8][2], bl[8][2];
            #pragma unroll
            for (int nt = 0; nt < 8; nt++) {
                const int col = wn * 64 + nt * 8 + gid;
                const int o = col * (RSTR * 2) + kb;
                bh[nt][0] = *(const uint32_t*)(pBh + o);
                bh[nt][1] = *(const uint32_t*)(pBh + o + 16);
                bl[nt][0] = *(const uint32_t*)(pBl + o);
                bl[nt][1] = *(const uint32_t*)(pBl + o + 16);
            }
            uint32_t av[4][4];
            #pragma unroll
            for (int mt = 0; mt < 4; mt++) {
                const int r0 = (wm * 64 + mt * 16 + gid) * (RSTR * 2) + kb;
                const int r1 = r0 + 8 * (RSTR * 2);
                av[mt][0] = *(const uint32_t*)(pA + r0);
                av[mt][1] = *(const uint32_t*)(pA + r1);
                av[mt][2] = *(const uint32_t*)(pA + r0 + 16);
                av[mt][3] = *(const uint32_t*)(pA + r1 + 16);
            }

            #pragma unroll
            for (int mt = 0; mt < 4; mt++)
                #pragma unroll
                for (int nt = 0; nt < 8; nt++)
                    mma_f16(acc[mt][nt], av[mt], bh[nt]);   // a * b_hi
            #pragma unroll
            for (int mt = 0; mt < 4; mt++)
                #pragma unroll
                for (int nt = 0; nt < 8; nt++)
                    mma_f16(acc[mt][nt], av[mt], bl[nt]);   // a * b_lo
        }

        cb = (cb == 2) ? 0 : cb + 1;
        pb = (pb == 2) ? 0 : pb + 1;
    }
    #undef LOADCHUNK

    // epilogue
    #pragma unroll
    for (int nt = 0; nt < 8; nt++) {
        const int col = bn0 + wn * 64 + nt * 8 + tg * 2;
        const float2 bv = *(const float2*)(bias + col);
        #pragma unroll
        for (int mt = 0; mt < 4; mt++) {
            const int r0 = bm0 + wm * 64 + mt * 16 + gid;
            float2 o0 = make_float2(acc[mt][nt][0] + bv.x, acc[mt][nt][1] + bv.y);
            float2 o1 = make_float2(acc[mt][nt][2] + bv.x, acc[mt][nt][3] + bv.y);
            *(float2*)(C + (size_t)r0 * N + col)       = o0;
            *(float2*)(C + (size_t)(r0 + 8) * N + col) = o1;
        }
    }
}

// ---------------------------------------------------------------------------
// Elementwise convert fp32 -> fp16 (hi only), vectorized
// ---------------------------------------------------------------------------
__global__ __launch_bounds__(256)
void tohalf_kernel(const float* __restrict__ in, __half* __restrict__ out, int n4)
{
    int i = blockIdx.x * 256 + threadIdx.x;
    if (i >= n4) return;
    float4 v = ((const float4*)in)[i];
    __half2 p0 = __floats2half2_rn(v.x, v.y);
    __half2 p1 = __floats2half2_rn(v.z, v.w);
    ((uint2*)out)[i] = make_uint2(*(uint32_t*)&p0, *(uint32_t*)&p1);
}

// ---------------------------------------------------------------------------
// Transpose + split: w[512, Ndim] fp32 -> hi/lo [Ndim, 512] fp16
// ---------------------------------------------------------------------------
__global__ __launch_bounds__(256)
void splitT_kernel(const float* __restrict__ w, __half* __restrict__ hi,
                   __half* __restrict__ lo, int Ndim)
{
    __shared__ float t[32][33];
    const int k0 = blockIdx.x * 32;
    const int n0 = blockIdx.y * 32;
    const int tx = threadIdx.x, ty = threadIdx.y;
    #pragma unroll
    for (int r = 0; r < 32; r += 8)
        t[ty + r][tx] = w[(size_t)(k0 + ty + r) * Ndim + n0 + tx];
    __syncthreads();
    #pragma unroll
    for (int r = 0; r < 32; r += 8) {
        float v = t[tx][ty + r];
        __half h, l;
        fp16split(v, h, l);
        const size_t idx = (size_t)(n0 + ty + r) * KK + k0 + tx;
        hi[idx] = h;
        lo[idx] = l;
    }
}

// ---------------------------------------------------------------------------
// Neighborhood attention: thread-per-l, stride-33 smem, writes fp16 output
// ---------------------------------------------------------------------------
#define LT 128
#define WR (LT + KWX - 1)       // 140
#define SSTR 33

__global__ __launch_bounds__(128)
void natten1d_kernel(const float* __restrict__ rpb)
{
    __shared__ float sk[WR * SSTR];
    __shared__ float sv[WR * SSTR];
    __shared__ float srpb[NRPBX];

    const int tid  = threadIdx.x;
    const int warp = tid >> 5;
    const int lane = tid & 31;
    const int l0 = blockIdx.x * LT;
    const int h  = blockIdx.y;
    const int b  = blockIdx.z;
    const int base = l0 - KHX;

    const float* qb = g_qkv + (size_t)b * LLX * (3 * CCX) + h * HDX;
    const float* kb = qb + CCX;
    const float* vb = qb + 2 * CCX;

    if (tid < NRPBX) srpb[tid] = rpb[h * NRPBX + tid];

    for (int r = warp; r < WR; r += 4) {
        const int gr = base + r;
        if (gr >= 0 && gr < LLX) {
            sk[r * SSTR + lane] = kb[(size_t)gr * (3 * CCX) + lane];
            sv[r * SSTR + lane] = vb[(size_t)gr * (3 * CCX) + lane];
        }
    }
    __syncthreads();

    const int l = l0 + tid;
    int ni = l - KHX;
    if (ni < 0) ni = 0;
    if (ni > LLX - KWX) ni = LLX - KWX;
    const int roff = ni - l + (KWX - 1);
    const int s0 = ni - base;

    const float scale = 0.17677669529663687f;
    float q[HDX];
    {
        const float* qp = qb + (size_t)l * (3 * CCX);
        #pragma unroll
        for (int d4 = 0; d4 < HDX; d4 += 4) {
            float4 v = *(const float4*)(qp + d4);
            q[d4 + 0] = v.x * scale; q[d4 + 1] = v.y * scale;
            q[d4 + 2] = v.z * scale; q[d4 + 3] = v.w * scale;
        }
    }

    float sc[KWX];
    float smax = -1e30f;
    #pragma unroll
    for (int j = 0; j < KWX; j++) {
        const float* kr = &sk[(s0 + j) * SSTR];
        float s = 0.f;
        #pragma unroll
        for (int d = 0; d < HDX; d++) s = fmaf(q[d], kr[d], s);
        s += srpb[roff + j];
        sc[j] = s;
        smax = fmaxf(smax, s);
    }
    float ssum = 0.f;
    #pragma unroll
    for (int j = 0; j < KWX; j++) {
        sc[j] = __expf(sc[j] - smax);
        ssum += sc[j];
    }
    const float inv = 1.f / ssum;

    float acc[HDX];
    #pragma unroll
    for (int d = 0; d < HDX; d++) acc[d] = 0.f;
    #pragma unroll
    for (int j = 0; j < KWX; j++) {
        const float* vr = &sv[(s0 + j) * SSTR];
        const float p = sc[j];
        #pragma unroll
        for (int d = 0; d < HDX; d++) acc[d] = fmaf(p, vr[d], acc[d]);
    }

    __half* oh = g_at + (size_t)(b * LLX + l) * CCX + h * HDX;
    #pragma unroll
    for (int d2 = 0; d2 < HDX; d2 += 2) {
        __half2 hp = __floats2half2_rn(acc[d2] * inv, acc[d2 + 1] * inv);
        *(uint32_t*)(oh + d2) = *(uint32_t*)&hp;
    }
}

// ---------------------------------------------------------------------------
extern "C" void kernel_launch(void* const* d_in, const int* in_sizes, int n_in,
                              void* d_out, int out_size)
{
    const float* x      = (const float*)d_in[0];
    const float* qkv_w  = (const float*)d_in[1];
    const float* qkv_b  = (const float*)d_in[2];
    const float* rpb    = (const float*)d_in[3];
    const float* proj_w = (const float*)d_in[4];
    const float* proj_b = (const float*)d_in[5];
    float* out = (float*)d_out;

    float* qkv;
    __half *xa, *at, *w1h, *w1l, *w2h, *w2l;
    cudaGetSymbolAddress((void**)&qkv, g_qkv);
    cudaGetSymbolAddress((void**)&xa,  g_xa);
    cudaGetSymbolAddress((void**)&at,  g_at);
    cudaGetSymbolAddress((void**)&w1h, g_w1_hi);
    cudaGetSymbolAddress((void**)&w1l, g_w1_lo);
    cudaGetSymbolAddress((void**)&w2h, g_w2_hi);
    cudaGetSymbolAddress((void**)&w2l, g_w2_lo);

    cudaFuncSetAttribute(fp16x2_gemm,
                         cudaFuncAttributeMaxDynamicSharedMemorySize, GEMM_SMEM);

    // 1) conversions / splits
    {
        int n4 = MLX * CCX / 4;
        tohalf_kernel<<<(n4 + 255) / 256, 256>>>(x, xa, n4);
    }
    {
        dim3 grid(KK / 32, (3 * CCX) / 32);
        splitT_kernel<<<grid, dim3(32, 8)>>>(qkv_w, w1h, w1l, 3 * CCX);
    }
    {
        dim3 grid(KK / 32, CCX / 32);
        splitT_kernel<<<grid, dim3(32, 8)>>>(proj_w, w2h, w2l, CCX);
    }

    // 2) QKV GEMM: [16384,512] x [1536,512]^T -> g_qkv
    {
        dim3 grid((3 * CCX) / 128, MLX / 128);
        fp16x2_gemm<<<grid, 128, GEMM_SMEM>>>(xa, w1h, w1l, qkv_b, qkv, 3 * CCX);
    }

    // 3) attention
    {
        dim3 grid(LLX / LT, HHX, BBX);
        natten1d_kernel<<<grid, 128>>>(rpb);
    }

    // 4) proj GEMM: [16384,512] x [512,512]^T -> out
    {
        dim3 grid(CCX / 128, MLX / 128);
        fp16x2_gemm<<<grid, 128, GEMM_SMEM>>>(at, w2h, w2l, proj_b, out, CCX);
    }
}

// round 9
// speedup vs baseline: 1.8862x; 1.3770x over previous
#include <cuda_runtime.h>
#include <cuda_fp16.h>
#include <cstdint>
#include <math.h>

// Problem constants
#define BBX 4
#define LLX 4096
#define CCX 512
#define HHX 16
#define HDX 32
#define KWX 13
#define KHX 6
#define NRPBX 25
#define MLX (BBX*LLX)          // 16384
#define KK  512

// ---------------------------------------------------------------------------
// Global scratch
// ---------------------------------------------------------------------------
__device__ float g_qkv[(size_t)MLX * (3 * CCX)];
__device__ __half g_xa[(size_t)MLX * CCX];             // x as fp16
__device__ __half g_at[(size_t)MLX * CCX];             // attn out fp16
__device__ __half g_w1[(size_t)(3*CCX) * CCX];         // qkv_w^T [1536,512] fp16
__device__ __half g_w2[(size_t)CCX * CCX];             // proj_w^T [512,512] fp16

// ---------------------------------------------------------------------------
// Helpers
// ---------------------------------------------------------------------------
__device__ __forceinline__ uint32_t sptr(const void* p) {
    return (uint32_t)__cvta_generic_to_shared(p);
}
__device__ __forceinline__ void cp16(uint32_t s, const void* g) {
    asm volatile("cp.async.cg.shared.global [%0], [%1], 16;\n" :: "r"(s), "l"(g));
}
__device__ __forceinline__ void cp_commit() {
    asm volatile("cp.async.commit_group;\n" ::: "memory");
}
__device__ __forceinline__ void cp_wait0() {
    asm volatile("cp.async.wait_group 0;\n" ::: "memory");
}
__device__ __forceinline__ void cp_wait1() {
    asm volatile("cp.async.wait_group 1;\n" ::: "memory");
}
__device__ __forceinline__ void mma_f16(float* c, const uint32_t* a, const uint32_t* b) {
    asm volatile(
        "mma.sync.aligned.m16n8k16.row.col.f32.f16.f16.f32 "
        "{%0,%1,%2,%3}, {%4,%5,%6,%7}, {%8,%9}, {%0,%1,%2,%3};\n"
        : "+f"(c[0]), "+f"(c[1]), "+f"(c[2]), "+f"(c[3])
        : "r"(a[0]), "r"(a[1]), "r"(a[2]), "r"(a[3]), "r"(b[0]), "r"(b[1]));
}

// ---------------------------------------------------------------------------
// fp16 GEMM: C[M,N] = A[M,512] x (B[N,512])^T + bias   (single MMA per k16)
// 128x128 CTA tile, 128 threads (4 warps 2x2, warp tile 64x64),
// BK=32, 3-stage cp.async ring.
// ---------------------------------------------------------------------------
#define RSTR 40                      // fp16 row stride (80 B, conflict-free)
#define TILE_B (128u * RSTR * 2u)    // 10240 B
#define STAGE_B (2u * TILE_B)        // 20480 B  (A, B)
#define GEMM_SMEM (3u * STAGE_B)     // 61440 B

__global__ __launch_bounds__(128, 2)
void fp16_gemm(const __half* __restrict__ A, const __half* __restrict__ B,
               const float* __restrict__ bias, float* __restrict__ C, int N)
{
    extern __shared__ char smem[];

    const int tid  = threadIdx.x;
    const int warp = tid >> 5;     // 0..3
    const int lane = tid & 31;
    const int wm   = warp & 1;     // 64-row slab
    const int wn   = warp >> 1;    // 64-col slab
    const int gid  = lane >> 2;    // 0..7
    const int tg   = lane & 3;     // 0..3

    const int bm0 = blockIdx.y * 128;
    const int bn0 = blockIdx.x * 128;

    const __half* t0 = A + (size_t)bm0 * KK;
    const __half* t1 = B + (size_t)bn0 * KK;
    const uint32_t sbase = sptr(smem);

    #define LOADCHUNK(c, bufb) do { \
        const uint32_t sm0 = sbase + (bufb) * STAGE_B; \
        const __half* gp0 = t0 + (c) * 32; \
        const __half* gp1 = t1 + (c) * 32; \
        _Pragma("unroll") \
        for (int i_ = 0; i_ < 4; i_++) { \
            int u_ = i_ * 128 + tid; \
            int row_ = u_ >> 2; \
            int c16_ = u_ & 3; \
            uint32_t so_ = (uint32_t)(row_ * (RSTR * 2) + c16_ * 16); \
            size_t go_ = (size_t)row_ * KK + c16_ * 8; \
            cp16(sm0 + so_,          gp0 + go_); \
            cp16(sm0 + TILE_B + so_, gp1 + go_); \
        } \
        cp_commit(); \
    } while (0)

    float acc[4][8][4];
    #pragma unroll
    for (int mt = 0; mt < 4; mt++)
        #pragma unroll
        for (int nt = 0; nt < 8; nt++)
            #pragma unroll
            for (int c = 0; c < 4; c++) acc[mt][nt][c] = 0.f;

    const int nT = KK / 32;          // 16

    LOADCHUNK(0, 0);
    LOADCHUNK(1, 1);

    int cb = 0, pb = 2;
    for (int t = 0; t < nT; t++) {
        if (t == nT - 1) cp_wait0(); else cp_wait1();
        __syncthreads();

        if (t + 2 < nT) LOADCHUNK(t + 2, pb);

        const char* stage = smem + (uint32_t)cb * STAGE_B;
        const char* pA = stage;
        const char* pB = stage + TILE_B;

        #pragma unroll
        for (int ks = 0; ks < 2; ks++) {
            const int kb = ks * 32 + tg * 4;

            uint32_t bv[8][2];
            #pragma unroll
            for (int nt = 0; nt < 8; nt++) {
                const int col = wn * 64 + nt * 8 + gid;
                const int o = col * (RSTR * 2) + kb;
                bv[nt][0] = *(const uint32_t*)(pB + o);
                bv[nt][1] = *(const uint32_t*)(pB + o + 16);
            }
            uint32_t av[4][4];
            #pragma unroll
            for (int mt = 0; mt < 4; mt++) {
                const int r0 = (wm * 64 + mt * 16 + gid) * (RSTR * 2) + kb;
                const int r1 = r0 + 8 * (RSTR * 2);
                av[mt][0] = *(const uint32_t*)(pA + r0);
                av[mt][1] = *(const uint32_t*)(pA + r1);
                av[mt][2] = *(const uint32_t*)(pA + r0 + 16);
                av[mt][3] = *(const uint32_t*)(pA + r1 + 16);
            }

            #pragma unroll
            for (int mt = 0; mt < 4; mt++)
                #pragma unroll
                for (int nt = 0; nt < 8; nt++)
                    mma_f16(acc[mt][nt], av[mt], bv[nt]);
        }

        cb = (cb == 2) ? 0 : cb + 1;
        pb = (pb == 2) ? 0 : pb + 1;
    }
    #undef LOADCHUNK

    // epilogue
    #pragma unroll
    for (int nt = 0; nt < 8; nt++) {
        const int col = bn0 + wn * 64 + nt * 8 + tg * 2;
        const float2 bvv = *(const float2*)(bias + col);
        #pragma unroll
        for (int mt = 0; mt < 4; mt++) {
            const int r0 = bm0 + wm * 64 + mt * 16 + gid;
            float2 o0 = make_float2(acc[mt][nt][0] + bvv.x, acc[mt][nt][1] + bvv.y);
            float2 o1 = make_float2(acc[mt][nt][2] + bvv.x, acc[mt][nt][3] + bvv.y);
            *(float2*)(C + (size_t)r0 * N + col)       = o0;
            *(float2*)(C + (size_t)(r0 + 8) * N + col) = o1;
        }
    }
}

// ---------------------------------------------------------------------------
// Elementwise convert fp32 -> fp16
// ---------------------------------------------------------------------------
__global__ __launch_bounds__(256)
void tohalf_kernel(const float* __restrict__ in, __half* __restrict__ out, int n4)
{
    int i = blockIdx.x * 256 + threadIdx.x;
    if (i >= n4) return;
    float4 v = ((const float4*)in)[i];
    __half2 p0 = __floats2half2_rn(v.x, v.y);
    __half2 p1 = __floats2half2_rn(v.z, v.w);
    ((uint2*)out)[i] = make_uint2(*(uint32_t*)&p0, *(uint32_t*)&p1);
}

// ---------------------------------------------------------------------------
// Transpose + convert: w[512, Ndim] fp32 -> [Ndim, 512] fp16
// ---------------------------------------------------------------------------
__global__ __launch_bounds__(256)
void halfT_kernel(const float* __restrict__ w, __half* __restrict__ out, int Ndim)
{
    __shared__ float t[32][33];
    const int k0 = blockIdx.x * 32;
    const int n0 = blockIdx.y * 32;
    const int tx = threadIdx.x, ty = threadIdx.y;
    #pragma unroll
    for (int r = 0; r < 32; r += 8)
        t[ty + r][tx] = w[(size_t)(k0 + ty + r) * Ndim + n0 + tx];
    __syncthreads();
    #pragma unroll
    for (int r = 0; r < 32; r += 8) {
        float v = t[tx][ty + r];
        out[(size_t)(n0 + ty + r) * KK + k0 + tx] = __float2half_rn(v);
    }
}

// ---------------------------------------------------------------------------
// Neighborhood attention: thread-per-l, stride-33 smem, fp16 output
// ---------------------------------------------------------------------------
#define LT 128
#define WR (LT + KWX - 1)       // 140
#define SSTR 33

__global__ __launch_bounds__(128)
void natten1d_kernel(const float* __restrict__ rpb)
{
    __shared__ float sk[WR * SSTR];
    __shared__ float sv[WR * SSTR];
    __shared__ float srpb[NRPBX];

    const int tid  = threadIdx.x;
    const int warp = tid >> 5;
    const int lane = tid & 31;
    const int l0 = blockIdx.x * LT;
    const int h  = blockIdx.y;
    const int b  = blockIdx.z;
    const int base = l0 - KHX;

    const float* qb = g_qkv + (size_t)b * LLX * (3 * CCX) + h * HDX;
    const float* kb = qb + CCX;
    const float* vb = qb + 2 * CCX;

    if (tid < NRPBX) srpb[tid] = rpb[h * NRPBX + tid];

    for (int r = warp; r < WR; r += 4) {
        const int gr = base + r;
        if (gr >= 0 && gr < LLX) {
            sk[r * SSTR + lane] = kb[(size_t)gr * (3 * CCX) + lane];
            sv[r * SSTR + lane] = vb[(size_t)gr * (3 * CCX) + lane];
        }
    }
    __syncthreads();

    const int l = l0 + tid;
    int ni = l - KHX;
    if (ni < 0) ni = 0;
    if (ni > LLX - KWX) ni = LLX - KWX;
    const int roff = ni - l + (KWX - 1);
    const int s0 = ni - base;

    const float scale = 0.17677669529663687f;
    float q[HDX];
    {
        const float* qp = qb + (size_t)l * (3 * CCX);
        #pragma unroll
        for (int d4 = 0; d4 < HDX; d4 += 4) {
            float4 v = *(const float4*)(qp + d4);
            q[d4 + 0] = v.x * scale; q[d4 + 1] = v.y * scale;
            q[d4 + 2] = v.z * scale; q[d4 + 3] = v.w * scale;
        }
    }

    float sc[KWX];
    float smax = -1e30f;
    #pragma unroll
    for (int j = 0; j < KWX; j++) {
        const float* kr = &sk[(s0 + j) * SSTR];
        float s = 0.f;
        #pragma unroll
        for (int d = 0; d < HDX; d++) s = fmaf(q[d], kr[d], s);
        s += srpb[roff + j];
        sc[j] = s;
        smax = fmaxf(smax, s);
    }
    float ssum = 0.f;
    #pragma unroll
    for (int j = 0; j < KWX; j++) {
        sc[j] = __expf(sc[j] - smax);
        ssum += sc[j];
    }
    const float inv = 1.f / ssum;

    float acc[HDX];
    #pragma unroll
    for (int d = 0; d < HDX; d++) acc[d] = 0.f;
    #pragma unroll
    for (int j = 0; j < KWX; j++) {
        const float* vr = &sv[(s0 + j) * SSTR];
        const float p = sc[j];
        #pragma unroll
        for (int d = 0; d < HDX; d++) acc[d] = fmaf(p, vr[d], acc[d]);
    }

    __half* oh = g_at + (size_t)(b * LLX + l) * CCX + h * HDX;
    #pragma unroll
    for (int d2 = 0; d2 < HDX; d2 += 2) {
        __half2 hp = __floats2half2_rn(acc[d2] * inv, acc[d2 + 1] * inv);
        *(uint32_t*)(oh + d2) = *(uint32_t*)&hp;
    }
}

// ---------------------------------------------------------------------------
extern "C" void kernel_launch(void* const* d_in, const int* in_sizes, int n_in,
                              void* d_out, int out_size)
{
    const float* x      = (const float*)d_in[0];
    const float* qkv_w  = (const float*)d_in[1];
    const float* qkv_b  = (const float*)d_in[2];
    const float* rpb    = (const float*)d_in[3];
    const float* proj_w = (const float*)d_in[4];
    const float* proj_b = (const float*)d_in[5];
    float* out = (float*)d_out;

    float* qkv;
    __half *xa, *at, *w1, *w2;
    cudaGetSymbolAddress((void**)&qkv, g_qkv);
    cudaGetSymbolAddress((void**)&xa,  g_xa);
    cudaGetSymbolAddress((void**)&at,  g_at);
    cudaGetSymbolAddress((void**)&w1,  g_w1);
    cudaGetSymbolAddress((void**)&w2,  g_w2);

    cudaFuncSetAttribute(fp16_gemm,
                         cudaFuncAttributeMaxDynamicSharedMemorySize, GEMM_SMEM);

    // 1) conversions
    {
        int n4 = MLX * CCX / 4;
        tohalf_kernel<<<(n4 + 255) / 256, 256>>>(x, xa, n4);
    }
    {
        dim3 grid(KK / 32, (3 * CCX) / 32);
        halfT_kernel<<<grid, dim3(32, 8)>>>(qkv_w, w1, 3 * CCX);
    }
    {
        dim3 grid(KK / 32, CCX / 32);
        halfT_kernel<<<grid, dim3(32, 8)>>>(proj_w, w2, CCX);
    }

    // 2) QKV GEMM: [16384,512] x [1536,512]^T -> g_qkv
    {
        dim3 grid((3 * CCX) / 128, MLX / 128);
        fp16_gemm<<<grid, 128, GEMM_SMEM>>>(xa, w1, qkv_b, qkv, 3 * CCX);
    }

    // 3) attention
    {
        dim3 grid(LLX / LT, HHX, BBX);
        natten1d_kernel<<<grid, 128>>>(rpb);
    }

    // 4) proj GEMM: [16384,512] x [512,512]^T -> out
    {
        dim3 grid(CCX / 128, MLX / 128);
        fp16_gemm<<<grid, 128, GEMM_SMEM>>>(at, w2, proj_b, out, CCX);
    }
}

// round 10
// speedup vs baseline: 2.1284x; 1.1284x over previous
#include <cuda_runtime.h>
#include <cuda_fp16.h>
#include <cstdint>
#include <math.h>

// Problem constants
#define BBX 4
#define LLX 4096
#define CCX 512
#define HHX 16
#define HDX 32
#define KWX 13
#define KHX 6
#define NRPBX 25
#define MLX (BBX*LLX)          // 16384
#define KK  512

// ---------------------------------------------------------------------------
// Global scratch
// ---------------------------------------------------------------------------
__device__ float g_qkv[(size_t)MLX * (3 * CCX)];
__device__ __half g_xa[(size_t)MLX * CCX];             // x as fp16
__device__ __half g_at[(size_t)MLX * CCX];             // attn out fp16
__device__ __half g_w1[(size_t)(3*CCX) * CCX];         // qkv_w^T [1536,512] fp16
__device__ __half g_w2[(size_t)CCX * CCX];             // proj_w^T [512,512] fp16

// ---------------------------------------------------------------------------
// Helpers
// ---------------------------------------------------------------------------
__device__ __forceinline__ uint32_t sptr(const void* p) {
    return (uint32_t)__cvta_generic_to_shared(p);
}
__device__ __forceinline__ void cp16(uint32_t s, const void* g) {
    asm volatile("cp.async.cg.shared.global [%0], [%1], 16;\n" :: "r"(s), "l"(g));
}
__device__ __forceinline__ void cp_commit() {
    asm volatile("cp.async.commit_group;\n" ::: "memory");
}
__device__ __forceinline__ void cp_wait0() {
    asm volatile("cp.async.wait_group 0;\n" ::: "memory");
}
__device__ __forceinline__ void cp_wait1() {
    asm volatile("cp.async.wait_group 1;\n" ::: "memory");
}
__device__ __forceinline__ void mma_f16(float* c, const uint32_t* a, const uint32_t* b) {
    asm volatile(
        "mma.sync.aligned.m16n8k16.row.col.f32.f16.f16.f32 "
        "{%0,%1,%2,%3}, {%4,%5,%6,%7}, {%8,%9}, {%0,%1,%2,%3};\n"
        : "+f"(c[0]), "+f"(c[1]), "+f"(c[2]), "+f"(c[3])
        : "r"(a[0]), "r"(a[1]), "r"(a[2]), "r"(a[3]), "r"(b[0]), "r"(b[1]));
}

// ---------------------------------------------------------------------------
// fp16 GEMM: C[M,N] = A[M,512] x (B[N,512])^T + bias
// 128x128 CTA tile, 128 threads (4 warps 2x2, warp tile 64x64),
// BK=64 (8 chunks), 2-stage cp.async ring, register-double-buffered frags.
// ---------------------------------------------------------------------------
#define RBYTES 144                   // bytes per 64-fp16 row (128 + 16 pad)
#define TILE_B (128u * RBYTES)       // 18432 B
#define STAGE_B (2u * TILE_B)        // 36864 B  (A, B)
#define GEMM_SMEM (2u * STAGE_B)     // 73728 B

__global__ __launch_bounds__(128, 2)
void fp16_gemm(const __half* __restrict__ A, const __half* __restrict__ B,
               const float* __restrict__ bias, float* __restrict__ C, int N)
{
    extern __shared__ char smem[];

    const int tid  = threadIdx.x;
    const int warp = tid >> 5;     // 0..3
    const int lane = tid & 31;
    const int wm   = warp & 1;     // 64-row slab
    const int wn   = warp >> 1;    // 64-col slab
    const int gid  = lane >> 2;    // 0..7
    const int tg   = lane & 3;     // 0..3

    const int bm0 = blockIdx.y * 128;
    const int bn0 = blockIdx.x * 128;

    const __half* t0 = A + (size_t)bm0 * KK;
    const __half* t1 = B + (size_t)bn0 * KK;
    const uint32_t sbase = sptr(smem);

    // chunk = 64 k-elements = 128 B/row. 128 rows x 8 cp16-units per operand.
    // 2048 units total / 128 threads = 16 cp16 per thread.
    #define LOADCHUNK(c, bufb) do { \
        const uint32_t sm0 = sbase + (bufb) * STAGE_B; \
        const __half* gp0 = t0 + (c) * 64; \
        const __half* gp1 = t1 + (c) * 64; \
        _Pragma("unroll") \
        for (int i_ = 0; i_ < 8; i_++) { \
            int u_ = i_ * 128 + tid; \
            int row_ = u_ >> 3; \
            int c16_ = u_ & 7; \
            uint32_t so_ = (uint32_t)(row_ * RBYTES + c16_ * 16); \
            size_t go_ = (size_t)row_ * KK + c16_ * 8; \
            cp16(sm0 + so_,          gp0 + go_); \
            cp16(sm0 + TILE_B + so_, gp1 + go_); \
        } \
        cp_commit(); \
    } while (0)

    // fragment load for k16 step ksv into register set s
    #define FLOADB(s, ksv) do { \
        _Pragma("unroll") \
        for (int nt_ = 0; nt_ < 8; nt_++) { \
            const int col_ = wn * 64 + nt_ * 8 + gid; \
            const int o_ = col_ * RBYTES + (ksv) * 32 + tg * 4; \
            bv[s][nt_][0] = *(const uint32_t*)(pB + o_); \
            bv[s][nt_][1] = *(const uint32_t*)(pB + o_ + 16); \
        } \
    } while (0)
    #define FLOADA(s, ksv) do { \
        _Pragma("unroll") \
        for (int mt_ = 0; mt_ < 4; mt_++) { \
            const int r0_ = (wm * 64 + mt_ * 16 + gid) * RBYTES + (ksv) * 32 + tg * 4; \
            const int r1_ = r0_ + 8 * RBYTES; \
            av[s][mt_][0] = *(const uint32_t*)(pA + r0_); \
            av[s][mt_][1] = *(const uint32_t*)(pA + r1_); \
            av[s][mt_][2] = *(const uint32_t*)(pA + r0_ + 16); \
            av[s][mt_][3] = *(const uint32_t*)(pA + r1_ + 16); \
        } \
    } while (0)

    float acc[4][8][4];
    #pragma unroll
    for (int mt = 0; mt < 4; mt++)
        #pragma unroll
        for (int nt = 0; nt < 8; nt++)
            #pragma unroll
            for (int c = 0; c < 4; c++) acc[mt][nt][c] = 0.f;

    const int nT = KK / 64;          // 8 chunks

    LOADCHUNK(0, 0);

    for (int t = 0; t < nT; t++) {
        if (t + 1 < nT) LOADCHUNK(t + 1, (t + 1) & 1);
        if (t + 1 < nT) cp_wait1(); else cp_wait0();
        __syncthreads();

        const char* stage = smem + (uint32_t)(t & 1) * STAGE_B;
        const char* pA = stage;
        const char* pB = stage + TILE_B;

        uint32_t av[2][4][4];
        uint32_t bv[2][8][2];

        FLOADB(0, 0);
        FLOADA(0, 0);
        #pragma unroll
        for (int ks = 0; ks < 4; ks++) {
            const int cs = ks & 1;
            if (ks < 3) {               // prefetch next step's fragments
                FLOADB(cs ^ 1, ks + 1);
                FLOADA(cs ^ 1, ks + 1);
            }
            #pragma unroll
            for (int mt = 0; mt < 4; mt++)
                #pragma unroll
                for (int nt = 0; nt < 8; nt++)
                    mma_f16(acc[mt][nt], av[cs][mt], bv[cs][nt]);
        }
        __syncthreads();
    }
    #undef LOADCHUNK
    #undef FLOADA
    #undef FLOADB

    // epilogue
    #pragma unroll
    for (int nt = 0; nt < 8; nt++) {
        const int col = bn0 + wn * 64 + nt * 8 + tg * 2;
        const float2 bvv = *(const float2*)(bias + col);
        #pragma unroll
        for (int mt = 0; mt < 4; mt++) {
            const int r0 = bm0 + wm * 64 + mt * 16 + gid;
            float2 o0 = make_float2(acc[mt][nt][0] + bvv.x, acc[mt][nt][1] + bvv.y);
            float2 o1 = make_float2(acc[mt][nt][2] + bvv.x, acc[mt][nt][3] + bvv.y);
            *(float2*)(C + (size_t)r0 * N + col)       = o0;
            *(float2*)(C + (size_t)(r0 + 8) * N + col) = o1;
        }
    }
}

// ---------------------------------------------------------------------------
// Elementwise convert fp32 -> fp16
// ---------------------------------------------------------------------------
__global__ __launch_bounds__(256)
void tohalf_kernel(const float* __restrict__ in, __half* __restrict__ out, int n4)
{
    int i = blockIdx.x * 256 + threadIdx.x;
    if (i >= n4) return;
    float4 v = ((const float4*)in)[i];
    __half2 p0 = __floats2half2_rn(v.x, v.y);
    __half2 p1 = __floats2half2_rn(v.z, v.w);
    ((uint2*)out)[i] = make_uint2(*(uint32_t*)&p0, *(uint32_t*)&p1);
}

// ---------------------------------------------------------------------------
// Transpose + convert: w[512, Ndim] fp32 -> [Ndim, 512] fp16
// ---------------------------------------------------------------------------
__global__ __launch_bounds__(256)
void halfT_kernel(const float* __restrict__ w, __half* __restrict__ out, int Ndim)
{
    __shared__ float t[32][33];
    const int k0 = blockIdx.x * 32;
    const int n0 = blockIdx.y * 32;
    const int tx = threadIdx.x, ty = threadIdx.y;
    #pragma unroll
    for (int r = 0; r < 32; r += 8)
        t[ty + r][tx] = w[(size_t)(k0 + ty + r) * Ndim + n0 + tx];
    __syncthreads();
    #pragma unroll
    for (int r = 0; r < 32; r += 8) {
        float v = t[tx][ty + r];
        out[(size_t)(n0 + ty + r) * KK + k0 + tx] = __float2half_rn(v);
    }
}

// ---------------------------------------------------------------------------
// Neighborhood attention: thread-per-l, stride-33 smem, fp16 output
// ---------------------------------------------------------------------------
#define LT 128
#define WR (LT + KWX - 1)       // 140
#define SSTR 33

__global__ __launch_bounds__(128)
void natten1d_kernel(const float* __restrict__ rpb)
{
    __shared__ float sk[WR * SSTR];
    __shared__ float sv[WR * SSTR];
    __shared__ float srpb[NRPBX];

    const int tid  = threadIdx.x;
    const int warp = tid >> 5;
    const int lane = tid & 31;
    const int l0 = blockIdx.x * LT;
    const int h  = blockIdx.y;
    const int b  = blockIdx.z;
    const int base = l0 - KHX;

    const float* qb = g_qkv + (size_t)b * LLX * (3 * CCX) + h * HDX;
    const float* kb = qb + CCX;
    const float* vb = qb + 2 * CCX;

    if (tid < NRPBX) srpb[tid] = rpb[h * NRPBX + tid];

    for (int r = warp; r < WR; r += 4) {
        const int gr = base + r;
        if (gr >= 0 && gr < LLX) {
            sk[r * SSTR + lane] = kb[(size_t)gr * (3 * CCX) + lane];
            sv[r * SSTR + lane] = vb[(size_t)gr * (3 * CCX) + lane];
        }
    }
    __syncthreads();

    const int l = l0 + tid;
    int ni = l - KHX;
    if (ni < 0) ni = 0;
    if (ni > LLX - KWX) ni = LLX - KWX;
    const int roff = ni - l + (KWX - 1);
    const int s0 = ni - base;

    const float scale = 0.17677669529663687f;
    float q[HDX];
    {
        const float* qp = qb + (size_t)l * (3 * CCX);
        #pragma unroll
        for (int d4 = 0; d4 < HDX; d4 += 4) {
            float4 v = *(const float4*)(qp + d4);
            q[d4 + 0] = v.x * scale; q[d4 + 1] = v.y * scale;
            q[d4 + 2] = v.z * scale; q[d4 + 3] = v.w * scale;
        }
    }

    float sc[KWX];
    float smax = -1e30f;
    #pragma unroll
    for (int j = 0; j < KWX; j++) {
        const float* kr = &sk[(s0 + j) * SSTR];
        float s = 0.f;
        #pragma unroll
        for (int d = 0; d < HDX; d++) s = fmaf(q[d], kr[d], s);
        s += srpb[roff + j];
        sc[j] = s;
        smax = fmaxf(smax, s);
    }
    float ssum = 0.f;
    #pragma unroll
    for (int j = 0; j < KWX; j++) {
        sc[j] = __expf(sc[j] - smax);
        ssum += sc[j];
    }
    const float inv = 1.f / ssum;

    float acc[HDX];
    #pragma unroll
    for (int d = 0; d < HDX; d++) acc[d] = 0.f;
    #pragma unroll
    for (int j = 0; j < KWX; j++) {
        const float* vr = &sv[(s0 + j) * SSTR];
        const float p = sc[j];
        #pragma unroll
        for (int d = 0; d < HDX; d++) acc[d] = fmaf(p, vr[d], acc[d]);
    }

    __half* oh = g_at + (size_t)(b * LLX + l) * CCX + h * HDX;
    #pragma unroll
    for (int d2 = 0; d2 < HDX; d2 += 2) {
        __half2 hp = __floats2half2_rn(acc[d2] * inv, acc[d2 + 1] * inv);
        *(uint32_t*)(oh + d2) = *(uint32_t*)&hp;
    }
}

// ---------------------------------------------------------------------------
extern "C" void kernel_launch(void* const* d_in, const int* in_sizes, int n_in,
                              void* d_out, int out_size)
{
    const float* x      = (const float*)d_in[0];
    const float* qkv_w  = (const float*)d_in[1];
    const float* qkv_b  = (const float*)d_in[2];
    const float* rpb    = (const float*)d_in[3];
    const float* proj_w = (const float*)d_in[4];
    const float* proj_b = (const float*)d_in[5];
    float* out = (float*)d_out;

    float* qkv;
    __half *xa, *at, *w1, *w2;
    cudaGetSymbolAddress((void**)&qkv, g_qkv);
    cudaGetSymbolAddress((void**)&xa,  g_xa);
    cudaGetSymbolAddress((void**)&at,  g_at);
    cudaGetSymbolAddress((void**)&w1,  g_w1);
    cudaGetSymbolAddress((void**)&w2,  g_w2);

    cudaFuncSetAttribute(fp16_gemm,
                         cudaFuncAttributeMaxDynamicSharedMemorySize, GEMM_SMEM);

    // 1) conversions
    {
        int n4 = MLX * CCX / 4;
        tohalf_kernel<<<(n4 + 255) / 256, 256>>>(x, xa, n4);
    }
    {
        dim3 grid(KK / 32, (3 * CCX) / 32);
        halfT_kernel<<<grid, dim3(32, 8)>>>(qkv_w, w1, 3 * CCX);
    }
    {
        dim3 grid(KK / 32, CCX / 32);
        halfT_kernel<<<grid, dim3(32, 8)>>>(proj_w, w2, CCX);
    }

    // 2) QKV GEMM: [16384,512] x [1536,512]^T -> g_qkv
    {
        dim3 grid((3 * CCX) / 128, MLX / 128);
        fp16_gemm<<<grid, 128, GEMM_SMEM>>>(xa, w1, qkv_b, qkv, 3 * CCX);
    }

    // 3) attention
    {
        dim3 grid(LLX / LT, HHX, BBX);
        natten1d_kernel<<<grid, 128>>>(rpb);
    }

    // 4) proj GEMM: [16384,512] x [512,512]^T -> out
    {
        dim3 grid(CCX / 128, MLX / 128);
        fp16_gemm<<<grid, 128, GEMM_SMEM>>>(at, w2, proj_b, out, CCX);
    }
}